// round 16
// baseline (speedup 1.0000x reference)
#include <cuda_runtime.h>
#include <cstdint>
#include <cstddef>

// SparseConv2D via mma.sync (tf32, m16n8k8) implicit GEMM, rolling 4-row strips.
// out(h,c,co) = sum_{ky,kx,ci} x(h+ky, c+kx, ci) * w[ky][kx][ci][co],
// gated per 14x14 block by max(mask) > 0.5 (precomputed into g_scale).
//
// R16: 2-row warps (A-fragment overlap across ky), 256-thr CTA computing 4
// output rows per iteration, 10-slot ring fed by cp.async (raw f32) with an
// in-place tf32 convert pass. 1 CTA/SM, one __syncthreads per 4 rows.

#define HIN   506
#define WIN   506
#define HOUT  504
#define WOUT  504
#define NB    36

#define NSTRIPS        32        // 8 batch * 4 column strips
#define CTAS_PER_STRIP 9
#define ROWS_PER_CTA   56        // 504 / 9, 14 iterations of 4 rows
#define GRID_MAIN      (NSTRIPS * CTAS_PER_STRIP)   // 288
#define NTHREADS       256

// smem word layout:
//  ring:  10 slots of [130 px][stride 36] -> 4680 words each (tf32 or raw f32)
//  BS:    swizzled B frags [9 tap][4 cc][4 s][32 lane] uint2 -> 9216 words
//  bias:  32 words
#define PATCH_STRIDE 36
#define KY_WORDS     (130 * PATCH_STRIDE)      // 4680
#define RING_SLOTS   10
#define BS_WOFF      (RING_SLOTS * KY_WORDS)   // 46800
#define BIAS_WOFF    (BS_WOFF + 9216)          // 56016
#define SMEM_WORDS   (BIAS_WOFF + 32)          // 56048
#define SMEM_BYTES   (SMEM_WORDS * 4)          // 224192 (~219 KB)

__device__ float g_scale[8 * NB * NB];

__device__ __forceinline__ uint32_t f2tf(float f) {
    uint32_t r;
    asm("cvt.rna.tf32.f32 %0, %1;" : "=r"(r) : "f"(f));
    return r;
}

__device__ __forceinline__ uint32_t smem_u32(const void* p) {
    uint32_t a;
    asm("{ .reg .u64 t; cvta.to.shared.u64 t, %1; cvt.u32.u64 %0, t; }"
        : "=r"(a) : "l"(p));
    return a;
}

__device__ __forceinline__ void mma_tf32(float* c, uint32_t a0, uint32_t a1,
                                         uint32_t a2, uint32_t a3,
                                         uint32_t b0, uint32_t b1) {
    asm volatile("mma.sync.aligned.m16n8k8.row.col.f32.tf32.tf32.f32 "
                 "{%0,%1,%2,%3}, {%4,%5,%6,%7}, {%8,%9}, {%0,%1,%2,%3};"
                 : "+f"(c[0]), "+f"(c[1]), "+f"(c[2]), "+f"(c[3])
                 : "r"(a0), "r"(a1), "r"(a2), "r"(a3), "r"(b0), "r"(b1));
}

// ---------------- mask precompute: one CTA per (n,bh,bw) ----------------
__global__ void mask_kernel(const float* __restrict__ mask) {
    __shared__ float red[8];
    int b = blockIdx.x;
    int n = b / (NB * NB);
    int rem = b % (NB * NB);
    int bh = rem / NB, bw = rem % NB;
    int tid = threadIdx.x;              // 256 = 16x16
    int r = tid >> 4, c = tid & 15;
    float m = mask[((size_t)(n * HIN + bh * 14 + r)) * WIN + bw * 14 + c];
    #pragma unroll
    for (int off = 16; off; off >>= 1)
        m = fmaxf(m, __shfl_xor_sync(0xffffffffu, m, off));
    if ((tid & 31) == 0) red[tid >> 5] = m;
    __syncthreads();
    if (tid == 0) {
        float mm = red[0];
        #pragma unroll
        for (int i = 1; i < 8; i++) mm = fmaxf(mm, red[i]);
        g_scale[b] = (mm > 0.5f) ? 1.0f : 0.0f;
    }
}

// ---------------- main kernel ----------------
__global__ __launch_bounds__(NTHREADS, 1)
void conv_mma_kernel(const float* __restrict__ x,
                     const float* __restrict__ wglob,
                     const float* __restrict__ bias,
                     float* __restrict__ out)
{
    extern __shared__ uint32_t sp[];
    const uint32_t sb32 = smem_u32(sp);
    const int tid  = threadIdx.x;
    const int wid  = tid >> 5;      // 0..7
    const int lane = tid & 31;
    const int g    = lane >> 2;     // fragment group row 0..7
    const int tq   = lane & 3;      // thread-in-group 0..3
    const int wrow = (wid >> 2) * 2;    // 0: rows h,h+1; 2: rows h+2,h+3
    const int pbase = (wid & 3) * 32;   // warp covers px [pbase, pbase+32)

    // ---- strip / row-range assignment ----
    const int strip  = blockIdx.x / CTAS_PER_STRIP;       // 0..31
    const int rchunk = blockIdx.x % CTAS_PER_STRIP;       // 0..8
    const int n      = strip >> 2;                        // batch
    const int c0     = (strip & 3) << 7;                  // col base
    const int hstart = rchunk * ROWS_PER_CTA;
    const int hend   = hstart + ROWS_PER_CTA;

    // ---- build B once per CTA (stage raw weights in ring area, then swizzle) ----
    {
        const float4* w4 = reinterpret_cast<const float4*>(wglob);
        float4* st4 = reinterpret_cast<float4*>(sp);
        #pragma unroll 1
        for (int i = tid; i < 9216 / 4; i += NTHREADS)
            st4[i] = w4[i];
    }
    if (tid < 32) sp[BIAS_WOFF + tid] = __float_as_uint(bias[tid]);
    __syncthreads();
    {
        const float* stage = reinterpret_cast<const float*>(sp);
        #pragma unroll 1
        for (int idx = tid; idx < 4608; idx += NTHREADS) {
            int l   = idx & 31;
            int s   = (idx >> 5) & 3;
            int cc  = (idx >> 7) & 3;
            int tap = idx >> 9;
            int k   = cc * 8 + (l & 3);
            int nn  = s * 8 + (l >> 2);
            uint32_t b0 = f2tf(stage[tap * 1024 + k * 32 + nn]);
            uint32_t b1 = f2tf(stage[tap * 1024 + (k + 4) * 32 + nn]);
            sp[BS_WOFF + idx * 2]     = b0;
            sp[BS_WOFF + idx * 2 + 1] = b1;
        }
    }
    __syncthreads();

    // ---- prologue: input rows hstart .. hstart+5 -> ring (tf32) ----
    #pragma unroll 1
    for (int id = tid; id < 6240; id += NTHREADS) {
        int row = hstart + id / 1040;
        int e   = id % 1040;
        int j   = e >> 3;
        int c4  = e & 7;
        int col = c0 + j; if (col > 505) col = 505;
        const float4 v = *reinterpret_cast<const float4*>(
            x + (((size_t)(n * HIN + row)) * WIN + col) * 32 + c4 * 4);
        uint32_t* dst = sp + (row % RING_SLOTS) * KY_WORDS + j * PATCH_STRIDE + c4 * 4;
        dst[0] = f2tf(v.x);
        dst[1] = f2tf(v.y);
        dst[2] = f2tf(v.z);
        dst[3] = f2tf(v.w);
    }
    __syncthreads();

    // ---- rolling sweep, 4 output rows per iteration ----
    #pragma unroll 1
    for (int h = hstart; h < hend; h += 4) {
        const int hw = h + wrow;            // warp's first output row
        const bool havepf = (h + 4 < hend);

        // issue cp.async for input rows h+6 .. h+9 (raw f32 into landing slots)
        if (havepf) {
            #pragma unroll
            for (int k = 0; k < 17; k++) {
                int id = tid + k * NTHREADS;
                if (id < 4160) {
                    int q  = id / 1040;          // 0..3
                    int e  = id % 1040;
                    int j  = e >> 3;
                    int c4 = e & 7;
                    int row = h + 6 + q;         // <= hend+1 <= 505
                    int col = c0 + j; if (col > 505) col = 505;
                    uint32_t dst = sb32 +
                        ((row % RING_SLOTS) * KY_WORDS + j * PATCH_STRIDE + c4 * 4) * 4;
                    const float* src =
                        x + (((size_t)(n * HIN + row)) * WIN + col) * 32 + c4 * 4;
                    asm volatile("cp.async.ca.shared.global [%0], [%1], 16;"
                                 :: "r"(dst), "l"(src));
                }
            }
            asm volatile("cp.async.commit_group;" ::: "memory");
        }

        // ---- compute: warp covers rows hw, hw+1 over px [pbase, pbase+32) ----
        float acc[2][2][4][4];   // [row][mtile][s][i]
        #pragma unroll
        for (int r = 0; r < 2; r++)
            #pragma unroll
            for (int m = 0; m < 2; m++)
                #pragma unroll
                for (int s = 0; s < 4; s++)
                    #pragma unroll
                    for (int i = 0; i < 4; i++) acc[r][m][s][i] = 0.0f;

        #pragma unroll
        for (int kx = 0; kx < 3; kx++) {
            uint32_t abase[4];
            #pragma unroll
            for (int r = 0; r < 4; r++)
                abase[r] = ((hw + r) % RING_SLOTS) * KY_WORDS +
                           (pbase + kx + g) * PATCH_STRIDE + tq;
            #pragma unroll
            for (int cc = 0; cc < 4; cc++) {
                uint32_t af[4][8];
                #pragma unroll
                for (int r = 0; r < 4; r++) {
                    const uint32_t* ar = sp + abase[r] + cc * 8;
                    af[r][0] = ar[0];
                    af[r][1] = ar[8 * PATCH_STRIDE];
                    af[r][2] = ar[4];
                    af[r][3] = ar[8 * PATCH_STRIDE + 4];
                    af[r][4] = ar[16 * PATCH_STRIDE];
                    af[r][5] = ar[24 * PATCH_STRIDE];
                    af[r][6] = ar[16 * PATCH_STRIDE + 4];
                    af[r][7] = ar[24 * PATCH_STRIDE + 4];
                }
                #pragma unroll
                for (int ky = 0; ky < 3; ky++) {
                    const uint32_t* br = sp + BS_WOFF + (ky * 3 + kx) * 1024 +
                                         cc * 256 + lane * 2;
                    #pragma unroll
                    for (int s = 0; s < 4; s++) {
                        const uint2 bb = *reinterpret_cast<const uint2*>(br + s * 64);
                        mma_tf32(acc[0][0][s], af[ky][0], af[ky][1],
                                 af[ky][2], af[ky][3], bb.x, bb.y);
                        mma_tf32(acc[0][1][s], af[ky][4], af[ky][5],
                                 af[ky][6], af[ky][7], bb.x, bb.y);
                        mma_tf32(acc[1][0][s], af[ky + 1][0], af[ky + 1][1],
                                 af[ky + 1][2], af[ky + 1][3], bb.x, bb.y);
                        mma_tf32(acc[1][1][s], af[ky + 1][4], af[ky + 1][5],
                                 af[ky + 1][6], af[ky + 1][7], bb.x, bb.y);
                    }
                }
            }
        }

        // ---- epilogue: rows hw, hw+1 ----
        {
            const float* bias_s = reinterpret_cast<const float*>(sp + BIAS_WOFF);
            #pragma unroll
            for (int r = 0; r < 2; r++) {
                const int hr = hw + r;
                const int srow = (n * NB + hr / 14) * NB;
                #pragma unroll
                for (int m = 0; m < 2; m++) {
                    const int colA = c0 + pbase + m * 16 + g;
                    const int colB = colA + 8;
                    float scA = 0.0f, scB = 0.0f;
                    if (colA < WOUT) scA = g_scale[srow + colA / 14];
                    if (colB < WOUT) scB = g_scale[srow + colB / 14];
                    float* opA = out + ((size_t)(n * HOUT + hr) * WOUT + colA) * 32;
                    float* opB = out + ((size_t)(n * HOUT + hr) * WOUT + colB) * 32;
                    #pragma unroll
                    for (int s = 0; s < 4; s++) {
                        const int co = s * 8 + 2 * tq;
                        const float b0 = bias_s[co], b1 = bias_s[co + 1];
                        if (colA < WOUT) {
                            float2 v = make_float2((acc[r][m][s][0] + b0) * scA,
                                                   (acc[r][m][s][1] + b1) * scA);
                            *reinterpret_cast<float2*>(opA + co) = v;
                        }
                        if (colB < WOUT) {
                            float2 v = make_float2((acc[r][m][s][2] + b0) * scB,
                                                   (acc[r][m][s][3] + b1) * scB);
                            *reinterpret_cast<float2*>(opB + co) = v;
                        }
                    }
                }
            }
        }

        // ---- convert landing rows in place (each thread converts its own chunks) ----
        if (havepf) {
            asm volatile("cp.async.wait_group 0;" ::: "memory");
            #pragma unroll
            for (int k = 0; k < 17; k++) {
                int id = tid + k * NTHREADS;
                if (id < 4160) {
                    int q  = id / 1040;
                    int e  = id % 1040;
                    int j  = e >> 3;
                    int c4 = e & 7;
                    int row = h + 6 + q;
                    uint32_t* p = sp + (row % RING_SLOTS) * KY_WORDS +
                                  j * PATCH_STRIDE + c4 * 4;
                    float4 v = *reinterpret_cast<const float4*>(p);
                    p[0] = f2tf(v.x);
                    p[1] = f2tf(v.y);
                    p[2] = f2tf(v.z);
                    p[3] = f2tf(v.w);
                }
            }
        }
        __syncthreads();   // ring reads done CTA-wide; converted rows visible
    }
}

extern "C" void kernel_launch(void* const* d_in, const int* in_sizes, int n_in,
                              void* d_out, int out_size)
{
    const float* x    = (const float*)d_in[0];
    const float* mask = (const float*)d_in[1];
    const float* w    = (const float*)d_in[2];
    const float* bias = (const float*)d_in[3];
    float* out        = (float*)d_out;
    (void)in_sizes; (void)n_in; (void)out_size;

    cudaFuncSetAttribute(conv_mma_kernel,
                         cudaFuncAttributeMaxDynamicSharedMemorySize, SMEM_BYTES);

    mask_kernel<<<8 * NB * NB, 256>>>(mask);
    conv_mma_kernel<<<GRID_MAIN, NTHREADS, SMEM_BYTES>>>(x, w, bias, out);
}